// round 5
// baseline (speedup 1.0000x reference)
#include <cuda_runtime.h>
#include <cuda_bf16.h>

// DynamicMaskHead (CondInst mask head) for GB300.
// Fixed problem shapes: N=2 images, Cin=8, H=100, W=152, n_inst=400,
// stride=8 -> factor=2, out = [400, 1, 200, 304] float32.

#define HH 100
#define WW 152
#define HWP (HH * WW)          // 15200 (divisible by 8)
#define NPARAM 169
#define MAXINST 400
#define OH (2 * HH)            // 200
#define OW (2 * WW)            // 304

// Scratch: per-instance logits at feature resolution. 400*15200*4B = 24.3 MB.
__device__ float g_logits[MAXINST * HWP];

__device__ __forceinline__ float2 ffma2(float2 a, float2 b, float2 c) {
    float2 d;
    asm("fma.rn.f32x2 %0, %1, %2, %3;"
        : "=l"(reinterpret_cast<unsigned long long &>(d))
        : "l"(reinterpret_cast<unsigned long long &>(a)),
          "l"(reinterpret_cast<unsigned long long &>(b)),
          "l"(reinterpret_cast<unsigned long long &>(c)));
    return d;
}

__device__ __forceinline__ float2 relu2(float2 a) {
    return make_float2(fmaxf(a.x, 0.0f), fmaxf(a.y, 0.0f));
}

// ---------------------------------------------------------------------------
// Kernel A: per-instance dynamic 3-layer MLP over all feature pixels.
// 8 consecutive pixels per thread (4 f32x2 lanes). Feature gather: two
// LDG.128 per channel. Weights pre-duplicated to float2 in shared; one
// broadcast LDS.64 per weight, amortized over 8 pixels.
// Register-liveness design: layer-0 accumulators h[4][8] are the only
// long-lived array; layers 1 and 2 are FUSED so layer-1 activations exist
// only 4 float2 at a time (peak ~160 live regs, no spill).
// Grid: (ceil(1900/256)=8, n_inst). Block: 256.
// ---------------------------------------------------------------------------
__global__ void __launch_bounds__(256)
mlp_kernel(const float* __restrict__ feats,      // [2, 8, H, W]
           const float* __restrict__ params,     // [n_inst, 169]
           const float* __restrict__ ilocs,      // [n_inst, 2]
           const int*   __restrict__ im_inds,    // [n_inst]
           const int*   __restrict__ fpn)        // [n_inst]
{
    __shared__ float2 w2s[NPARAM];
    __shared__ float s_locx, s_locy, s_invsoi;
    __shared__ int   s_base;

    const int inst = blockIdx.y;
    const int tid  = threadIdx.x;

    if (tid < NPARAM) {
        float ww = params[inst * NPARAM + tid];
        w2s[tid] = make_float2(ww, ww);
    }
    if (tid == 0) {
        s_locx = ilocs[inst * 2 + 0];
        s_locy = ilocs[inst * 2 + 1];
        int lvl = fpn[inst];
        // SOI = 64 * 2^lvl (exact powers of two)
        s_invsoi = 1.0f / (64.0f * (float)(1 << lvl));
        s_base = im_inds[inst] * 8 * HWP;
    }
    __syncthreads();

    // 8 consecutive pixels; HWP % 8 == 0 -> group all-in or all-out.
    const int p0 = (blockIdx.x * 256 + tid) * 8;
    if (p0 >= HWP) return;

    const float locx = s_locx, locy = s_locy, invsoi = s_invsoi;
    const int base = s_base;

    // ---- Layer 0 accumulators (4 lanes x 8 outputs), init with bias ----
    float2 h[4][8];
#pragma unroll
    for (int o = 0; o < 8; o++) {
        float2 b = w2s[152 + o];
#pragma unroll
        for (int l = 0; l < 4; l++) h[l][o] = b;
    }

    // rel coords for the 8 pixels (lane l holds px 2l, 2l+1)
    {
        int py = p0 / WW;
        int px = p0 % WW;
        float2 rx[4], ry[4];
#pragma unroll
        for (int l = 0; l < 4; l++) {
            float x0 = (locx - (float)(px * 8 + 4)) * invsoi;
            float y0 = (locy - (float)(py * 8 + 4)) * invsoi;
            if (++px == WW) { px = 0; py++; }
            float x1 = (locx - (float)(px * 8 + 4)) * invsoi;
            float y1 = (locy - (float)(py * 8 + 4)) * invsoi;
            if (++px == WW) { px = 0; py++; }
            rx[l] = make_float2(x0, x1);
            ry[l] = make_float2(y0, y1);
        }
#pragma unroll
        for (int o = 0; o < 8; o++) {
            float2 wx = w2s[o * 10 + 0];
            float2 wy = w2s[o * 10 + 1];
#pragma unroll
            for (int l = 0; l < 4; l++) {
                h[l][o] = ffma2(rx[l], wx, h[l][o]);
                h[l][o] = ffma2(ry[l], wy, h[l][o]);
            }
        }
    }

    // feature channels, accumulated one channel at a time
#pragma unroll
    for (int c = 0; c < 8; c++) {
        const float4 f0 = *reinterpret_cast<const float4*>(&feats[base + c * HWP + p0]);
        const float4 f1 = *reinterpret_cast<const float4*>(&feats[base + c * HWP + p0 + 4]);
        float2 x[4] = { make_float2(f0.x, f0.y), make_float2(f0.z, f0.w),
                        make_float2(f1.x, f1.y), make_float2(f1.z, f1.w) };
#pragma unroll
        for (int o = 0; o < 8; o++) {
            float2 wv = w2s[o * 10 + 2 + c];
#pragma unroll
            for (int l = 0; l < 4; l++)
                h[l][o] = ffma2(x[l], wv, h[l][o]);
        }
    }
#pragma unroll
    for (int o = 0; o < 8; o++)
#pragma unroll
        for (int l = 0; l < 4; l++) h[l][o] = relu2(h[l][o]);

    // ---- Layers 1+2 fused: for each hidden unit o, compute its layer-1
    // activation for the 4 lanes, ReLU, and fold into the final output. ----
    float2 out[4];
    {
        float2 b2 = w2s[168];
#pragma unroll
        for (int l = 0; l < 4; l++) out[l] = b2;
    }
#pragma unroll
    for (int o = 0; o < 8; o++) {
        float2 b1 = w2s[160 + o];
        float2 acc[4];
#pragma unroll
        for (int l = 0; l < 4; l++) acc[l] = b1;
#pragma unroll
        for (int i = 0; i < 8; i++) {
            float2 wv = w2s[80 + o * 8 + i];
#pragma unroll
            for (int l = 0; l < 4; l++)
                acc[l] = ffma2(h[l][i], wv, acc[l]);
        }
        float2 w2v = w2s[144 + o];
#pragma unroll
        for (int l = 0; l < 4; l++)
            out[l] = ffma2(relu2(acc[l]), w2v, out[l]);
    }

    float* op = &g_logits[inst * HWP + p0];
    *reinterpret_cast<float4*>(op)     = make_float4(out[0].x, out[0].y, out[1].x, out[1].y);
    *reinterpret_cast<float4*>(op + 4) = make_float4(out[2].x, out[2].y, out[3].x, out[3].y);
}

// ---------------------------------------------------------------------------
// Kernel B: aligned_bilinear, factor=2, zero-division formulation.
// For factor 2 (AdelaiDet semantics):
//   out[2k+1] = colexpand(row k)
//   out[2k]   = 0.5*(colexpand(row k-1) + colexpand(row k))   (row -1 := row 0)
// where colexpand(r)[2u+1] = r[u], colexpand(r)[2u] = 0.5*(r[u-1]+r[u])
// (r[-1] := r[0]).
// One block per (k, inst): stages rows k-1 and k in shared, writes two full
// output rows as float2 stores. No integer division anywhere.
// Grid: (HH, n_inst). Block: 160 (152 active lanes).
// ---------------------------------------------------------------------------
__global__ void __launch_bounds__(160)
upsample_kernel(float* __restrict__ out)
{
    __shared__ float sk[WW];    // row k
    __shared__ float skm[WW];   // row k-1 (== row k when k==0)

    const int k    = blockIdx.x;
    const int inst = blockIdx.y;
    const int u    = threadIdx.x;

    const float* rowk  = g_logits + inst * HWP + k * WW;
    const float* rowkm = (k > 0) ? (rowk - WW) : rowk;

    if (u < WW) {
        sk[u]  = rowk[u];
        skm[u] = rowkm[u];
    }
    __syncthreads();
    if (u >= WW) return;

    float a  = sk[u];
    float am = (u > 0) ? sk[u - 1]  : a;
    float b  = skm[u];
    float bm = (u > 0) ? skm[u - 1] : b;

    float ek0  = 0.5f * (am + a);   // colexpand(row k)[2u]
    float ek1  = a;                 // colexpand(row k)[2u+1]
    float ekm0 = 0.5f * (bm + b);
    float ekm1 = b;

    float* orow = out + ((size_t)inst * OH + 2 * k) * OW;
    // row 2k: 0.5*(e_km + e_k)  (k==0: skm==sk -> equals e_k, correct)
    reinterpret_cast<float2*>(orow)[u] =
        make_float2(0.5f * (ekm0 + ek0), 0.5f * (ekm1 + ek1));
    // row 2k+1: e_k
    reinterpret_cast<float2*>(orow + OW)[u] = make_float2(ek0, ek1);
}

extern "C" void kernel_launch(void* const* d_in, const int* in_sizes, int n_in,
                              void* d_out, int out_size)
{
    const float* feats   = (const float*)d_in[0];   // mask_feats [2,8,100,152]
    const float* params  = (const float*)d_in[1];   // [n_inst, 169]
    const float* ilocs   = (const float*)d_in[2];   // [n_inst, 2]
    const int*   im_inds = (const int*)d_in[3];     // [n_inst]
    const int*   fpn     = (const int*)d_in[4];     // [n_inst]

    int n_inst = in_sizes[3];
    if (n_inst > MAXINST) n_inst = MAXINST;

    dim3 gridA((HWP / 8 + 255) / 256, n_inst);
    mlp_kernel<<<gridA, 256>>>(feats, params, ilocs, im_inds, fpn);

    dim3 gridB(HH, n_inst);
    upsample_kernel<<<gridB, 160>>>((float*)d_out);
}

// round 6
// speedup vs baseline: 1.1675x; 1.1675x over previous
#include <cuda_runtime.h>
#include <cuda_bf16.h>

// DynamicMaskHead (CondInst mask head) for GB300.
// Fixed problem shapes: N=2 images, Cin=8, H=100, W=152, n_inst=400,
// stride=8 -> factor=2, out = [400, 1, 200, 304] float32.

#define HH 100
#define WW 152
#define HWP (HH * WW)          // 15200 (divisible by 4)
#define NPARAM 169
#define MAXINST 400
#define OH (2 * HH)            // 200
#define OW (2 * WW)            // 304
#define RB 4                   // k-rows per upsample block (100 % 4 == 0)

// Scratch: per-instance logits at feature resolution. 400*15200*4B = 24.3 MB.
__device__ float g_logits[MAXINST * HWP];

__device__ __forceinline__ float2 ffma2(float2 a, float2 b, float2 c) {
    float2 d;
    asm("fma.rn.f32x2 %0, %1, %2, %3;"
        : "=l"(reinterpret_cast<unsigned long long &>(d))
        : "l"(reinterpret_cast<unsigned long long &>(a)),
          "l"(reinterpret_cast<unsigned long long &>(b)),
          "l"(reinterpret_cast<unsigned long long &>(c)));
    return d;
}

__device__ __forceinline__ float2 relu2(float2 a) {
    return make_float2(fmaxf(a.x, 0.0f), fmaxf(a.y, 0.0f));
}

// ---------------------------------------------------------------------------
// Kernel A: per-instance dynamic 3-layer MLP over all feature pixels.
// 4 consecutive pixels per thread = 2 f32x2 lanes (the measured liveness
// sweet spot — 8 px/thread spilled). Incremental layer-0 accumulation: each
// feature channel is loaded (one LDG.128) and immediately FMA'd into the
// h accumulators, so no input-activation array is ever live. Layers 1+2 are
// fused: layer-1 activations exist only 2 float2 at a time.
// Peak liveness ~60 regs -> 3-4 CTAs/SM for LDS-latency hiding.
// Weights pre-duplicated to float2 in shared: one broadcast LDS.64 each.
// Grid: (15, n_inst). Block: 256.
// ---------------------------------------------------------------------------
__global__ void __launch_bounds__(256)
mlp_kernel(const float* __restrict__ feats,      // [2, 8, H, W]
           const float* __restrict__ params,     // [n_inst, 169]
           const float* __restrict__ ilocs,      // [n_inst, 2]
           const int*   __restrict__ im_inds,    // [n_inst]
           const int*   __restrict__ fpn)        // [n_inst]
{
    __shared__ float2 w2s[NPARAM];
    __shared__ float s_locx, s_locy, s_invsoi;
    __shared__ int   s_base;

    const int inst = blockIdx.y;
    const int tid  = threadIdx.x;

    if (tid < NPARAM) {
        float ww = params[inst * NPARAM + tid];
        w2s[tid] = make_float2(ww, ww);
    }
    if (tid == 0) {
        s_locx = ilocs[inst * 2 + 0];
        s_locy = ilocs[inst * 2 + 1];
        int lvl = fpn[inst];
        // SOI = 64 * 2^lvl (exact powers of two)
        s_invsoi = 1.0f / (64.0f * (float)(1 << lvl));
        s_base = im_inds[inst] * 8 * HWP;
    }
    __syncthreads();

    // 4 consecutive pixels; HWP % 4 == 0 -> group all-in or all-out.
    const int p0 = (blockIdx.x * 256 + tid) * 4;
    if (p0 >= HWP) return;

    const float locx = s_locx, locy = s_locy, invsoi = s_invsoi;
    const int base = s_base;

    // ---- Layer 0 accumulators (2 lanes x 8 outputs), init with bias ----
    float2 h[2][8];
#pragma unroll
    for (int o = 0; o < 8; o++) {
        float2 b = w2s[152 + o];
        h[0][o] = b;
        h[1][o] = b;
    }

    // rel coords for the 4 pixels (lane l holds px 2l, 2l+1)
    {
        int py = p0 / WW;
        int px = p0 % WW;
        float2 rx[2], ry[2];
#pragma unroll
        for (int l = 0; l < 2; l++) {
            float x0 = (locx - (float)(px * 8 + 4)) * invsoi;
            float y0 = (locy - (float)(py * 8 + 4)) * invsoi;
            if (++px == WW) { px = 0; py++; }
            float x1 = (locx - (float)(px * 8 + 4)) * invsoi;
            float y1 = (locy - (float)(py * 8 + 4)) * invsoi;
            if (++px == WW) { px = 0; py++; }
            rx[l] = make_float2(x0, x1);
            ry[l] = make_float2(y0, y1);
        }
#pragma unroll
        for (int o = 0; o < 8; o++) {
            float2 wx = w2s[o * 10 + 0];
            float2 wy = w2s[o * 10 + 1];
#pragma unroll
            for (int l = 0; l < 2; l++) {
                h[l][o] = ffma2(rx[l], wx, h[l][o]);
                h[l][o] = ffma2(ry[l], wy, h[l][o]);
            }
        }
    }

    // feature channels: load one LDG.128, fold in immediately
#pragma unroll
    for (int c = 0; c < 8; c++) {
        const float4 f = *reinterpret_cast<const float4*>(&feats[base + c * HWP + p0]);
        float2 x0 = make_float2(f.x, f.y);
        float2 x1 = make_float2(f.z, f.w);
#pragma unroll
        for (int o = 0; o < 8; o++) {
            float2 wv = w2s[o * 10 + 2 + c];
            h[0][o] = ffma2(x0, wv, h[0][o]);
            h[1][o] = ffma2(x1, wv, h[1][o]);
        }
    }
#pragma unroll
    for (int o = 0; o < 8; o++) {
        h[0][o] = relu2(h[0][o]);
        h[1][o] = relu2(h[1][o]);
    }

    // ---- Layers 1+2 fused ----
    float2 out0 = w2s[168];
    float2 out1 = out0;
#pragma unroll
    for (int o = 0; o < 8; o++) {
        float2 b1 = w2s[160 + o];
        float2 acc0 = b1;
        float2 acc1 = b1;
#pragma unroll
        for (int i = 0; i < 8; i++) {
            float2 wv = w2s[80 + o * 8 + i];
            acc0 = ffma2(h[0][i], wv, acc0);
            acc1 = ffma2(h[1][i], wv, acc1);
        }
        float2 w2v = w2s[144 + o];
        out0 = ffma2(relu2(acc0), w2v, out0);
        out1 = ffma2(relu2(acc1), w2v, out1);
    }

    *reinterpret_cast<float4*>(&g_logits[inst * HWP + p0]) =
        make_float4(out0.x, out0.y, out1.x, out1.y);
}

// ---------------------------------------------------------------------------
// Kernel B: aligned_bilinear, factor=2, zero-division formulation.
//   out[2k]   = 0.5*(colexpand(row k-1) + colexpand(row k))   (row -1 := row 0)
//   out[2k+1] = colexpand(row k)
//   colexpand(r)[2u] = 0.5*(r[u-1]+r[u]) (r[-1]:=r[0]);  [2u+1] = r[u]
// RB=4 k-rows per block: stage RB+1=5 contiguous logits rows via float4 into
// shared, each (u, r) thread writes 2 float2 (output rows 2k, 2k+1).
// Grid: (HH/RB=25, n_inst). Block: (160, 4) = 640 threads.
// ---------------------------------------------------------------------------
__global__ void __launch_bounds__(640)
upsample_kernel(float* __restrict__ out)
{
    __shared__ float s[RB + 1][WW];

    const int k0   = blockIdx.x * RB;
    const int inst = blockIdx.y;
    const int flat = threadIdx.y * 160 + threadIdx.x;

    // Stage rows k0-1 .. k0+RB-1 (clamped) as float4; WW/4 = 38 per row.
    if (flat < (RB + 1) * 38) {
        int j   = flat / 38;          // staged row index
        int c4  = flat - j * 38;      // float4 column
        int src = k0 - 1 + j;
        if (src < 0) src = 0;
        float4 v = *reinterpret_cast<const float4*>(
            &g_logits[inst * HWP + src * WW + c4 * 4]);
        *reinterpret_cast<float4*>(&s[j][c4 * 4]) = v;
    }
    __syncthreads();

    const int u = threadIdx.x;
    if (u >= WW) return;
    const int r = threadIdx.y;        // local k-row: k = k0 + r

    float a  = s[r + 1][u];                       // row k
    float am = (u > 0) ? s[r + 1][u - 1] : a;
    float b  = s[r][u];                           // row k-1 (== row k at k==0)
    float bm = (u > 0) ? s[r][u - 1] : b;

    float ek0  = 0.5f * (am + a);   // colexpand(row k)[2u]
    float ek1  = a;                 // colexpand(row k)[2u+1]
    float ekm0 = 0.5f * (bm + b);
    float ekm1 = b;

    float* orow = out + ((size_t)inst * OH + 2 * (k0 + r)) * OW;
    reinterpret_cast<float2*>(orow)[u] =
        make_float2(0.5f * (ekm0 + ek0), 0.5f * (ekm1 + ek1));   // row 2k
    reinterpret_cast<float2*>(orow + OW)[u] = make_float2(ek0, ek1); // row 2k+1
}

extern "C" void kernel_launch(void* const* d_in, const int* in_sizes, int n_in,
                              void* d_out, int out_size)
{
    const float* feats   = (const float*)d_in[0];   // mask_feats [2,8,100,152]
    const float* params  = (const float*)d_in[1];   // [n_inst, 169]
    const float* ilocs   = (const float*)d_in[2];   // [n_inst, 2]
    const int*   im_inds = (const int*)d_in[3];     // [n_inst]
    const int*   fpn     = (const int*)d_in[4];     // [n_inst]

    int n_inst = in_sizes[3];
    if (n_inst > MAXINST) n_inst = MAXINST;

    dim3 gridA((HWP / 4 + 255) / 256, n_inst);
    mlp_kernel<<<gridA, 256>>>(feats, params, ilocs, im_inds, fpn);

    dim3 gridB(HH / RB, n_inst);
    dim3 blockB(160, RB);
    upsample_kernel<<<gridB, blockB>>>((float*)d_out);
}